// round 3
// baseline (speedup 1.0000x reference)
#include <cuda_runtime.h>
#include <math.h>

// Problem constants
#define B_  2
#define S_  2048
#define D_  640        // = H_*DH_
#define H_  8
#define DH_ 80
#define M_  (B_*S_)    // 4096

// Scratch (device globals — no allocations allowed)
static __device__ float g_q[M_*D_];
static __device__ float g_k[M_*D_];
static __device__ float g_v[M_*D_];
static __device__ float g_attn[M_*D_];

// ---------------------------------------------------------------------------
// SGEMM: C[M,N] = A[M,K] @ W[K,N] (+bias), tiles 128x64x8, 256 threads,
// 8x4 per-thread micro-tile. M%128==0, N%64==0, K%8==0 assumed.
// ---------------------------------------------------------------------------
__global__ __launch_bounds__(256) void sgemm128x64(
    const float* __restrict__ A, const float* __restrict__ W,
    const float* __restrict__ bias, float* __restrict__ C,
    int Kdim, int Ndim)
{
    __shared__ float As[8][128];
    __shared__ float Bs[8][64];

    const int tid = threadIdx.x;
    const int tx = tid & 15;        // 16 col-groups of 4
    const int ty = tid >> 4;        // 16 row-groups of 8
    const int bm = blockIdx.y * 128;
    const int bn = blockIdx.x * 64;

    const int arow = tid >> 1;            // 0..127
    const int acol = (tid & 1) * 4;       // 0 or 4
    const int brow = tid >> 5;            // 0..7
    const int bcol = (tid & 31) * 2;      // 0..62

    float acc[8][4];
#pragma unroll
    for (int i = 0; i < 8; i++)
#pragma unroll
        for (int j = 0; j < 4; j++) acc[i][j] = 0.f;

    for (int k0 = 0; k0 < Kdim; k0 += 8) {
        float4 av = *(const float4*)(A + (bm + arow) * Kdim + k0 + acol);
        As[acol + 0][arow] = av.x;
        As[acol + 1][arow] = av.y;
        As[acol + 2][arow] = av.z;
        As[acol + 3][arow] = av.w;
        *(float2*)&Bs[brow][bcol] =
            *(const float2*)(W + (k0 + brow) * Ndim + bn + bcol);
        __syncthreads();

#pragma unroll
        for (int k = 0; k < 8; k++) {
            float a[8], b[4];
            *(float4*)&a[0] = *(const float4*)&As[k][ty * 8];
            *(float4*)&a[4] = *(const float4*)&As[k][ty * 8 + 4];
            *(float4*)&b[0] = *(const float4*)&Bs[k][tx * 4];
#pragma unroll
            for (int i = 0; i < 8; i++)
#pragma unroll
                for (int j = 0; j < 4; j++)
                    acc[i][j] = fmaf(a[i], b[j], acc[i][j]);
        }
        __syncthreads();
    }

    // epilogue
    float4 bv = make_float4(0.f, 0.f, 0.f, 0.f);
    if (bias) bv = *(const float4*)(bias + bn + tx * 4);
#pragma unroll
    for (int i = 0; i < 8; i++) {
        int row = bm + ty * 8 + i;
        float4 o;
        o.x = acc[i][0] + bv.x;
        o.y = acc[i][1] + bv.y;
        o.z = acc[i][2] + bv.z;
        o.w = acc[i][3] + bv.w;
        *(float4*)(C + row * Ndim + bn + tx * 4) = o;
    }
}

// ---------------------------------------------------------------------------
// Flash attention (fp32, online softmax).
// Grid: (S/64, H, B), 256 threads.
// Q/K tiles: 64 rows x 80, stored row-major with 8-row XOR swizzle on the
// float4 column index, row stride 96 floats (24 float4 slots).
// ---------------------------------------------------------------------------
#define BMQ 64
#define BNK 64
#define QK_STR 96   // floats per swizzled Q/K row
#define VS_STR 84   // floats per V row (80 + pad, float4-aligned)
#define PS_STR 65   // floats per P row (odd -> conflict-free scalar stores)
#define ATTN_SMEM_FLOATS (BMQ*QK_STR + BNK*QK_STR + BNK*VS_STR + BNK*PS_STR)
#define ATTN_SMEM_BYTES (ATTN_SMEM_FLOATS * 4)

__global__ __launch_bounds__(256) void flash_attn_kernel()
{
    extern __shared__ float sm[];
    float* Qs = sm;                       // 64*96
    float* Ks = Qs + BMQ * QK_STR;        // 64*96
    float* Vs = Ks + BNK * QK_STR;        // 64*84
    float* Ps = Vs + BNK * VS_STR;        // 64*65  (P transposed: [kv][q])

    const int tid = threadIdx.x;
    const int tx = tid & 15;   // kv-col group (4) in S-phase; out-col group (5) in PV
    const int ty = tid >> 4;   // q-row group (4)
    const int q0 = blockIdx.x * BMQ;
    const int h  = blockIdx.y;
    const int b  = blockIdx.z;

    const float SCALE = 0.11180339887498949f;  // 80^-0.5

    const float* qg = g_q + (b * S_ + q0) * D_ + h * DH_;
    const float* kg = g_k + (b * S_) * D_ + h * DH_;
    const float* vg = g_v + (b * S_) * D_ + h * DH_;

    // Load Q tile (swizzled)
    for (int idx = tid; idx < BMQ * 20; idx += 256) {
        int r = idx / 20, c4 = idx % 20;
        float4 v = *(const float4*)(qg + r * D_ + c4 * 4);
        *(float4*)&Qs[r * QK_STR + (c4 ^ (r & 7)) * 4] = v;
    }

    float m[4], l[4], o[4][5];
#pragma unroll
    for (int i = 0; i < 4; i++) {
        m[i] = -INFINITY;
        l[i] = 0.f;
#pragma unroll
        for (int j = 0; j < 5; j++) o[i][j] = 0.f;
    }

    for (int t = 0; t < S_ / BNK; t++) {
        const int kv0 = t * BNK;
        __syncthreads();  // previous iteration's reads of Ks/Vs/Ps done
        // Load K (swizzled) and V (plain) tiles
        for (int idx = tid; idx < BNK * 20; idx += 256) {
            int r = idx / 20, c4 = idx % 20;
            const float* rowk = kg + (kv0 + r) * D_ + c4 * 4;
            const float* rowv = vg + (kv0 + r) * D_ + c4 * 4;
            *(float4*)&Ks[r * QK_STR + (c4 ^ (r & 7)) * 4] = *(const float4*)rowk;
            *(float4*)&Vs[r * VS_STR + c4 * 4] = *(const float4*)rowv;
        }
        __syncthreads();

        // S = Q K^T  (4x4 per thread over the 64x64 tile)
        float s[4][4];
#pragma unroll
        for (int i = 0; i < 4; i++)
#pragma unroll
            for (int j = 0; j < 4; j++) s[i][j] = 0.f;

#pragma unroll 4
        for (int d4 = 0; d4 < 20; d4++) {
            float4 a[4], bb[4];
#pragma unroll
            for (int i = 0; i < 4; i++) {
                int r = ty * 4 + i;
                a[i] = *(const float4*)&Qs[r * QK_STR + ((d4 ^ (r & 7)) * 4)];
            }
#pragma unroll
            for (int j = 0; j < 4; j++) {
                int c = tx * 4 + j;
                bb[j] = *(const float4*)&Ks[c * QK_STR + ((d4 ^ (c & 7)) * 4)];
            }
#pragma unroll
            for (int i = 0; i < 4; i++)
#pragma unroll
                for (int j = 0; j < 4; j++) {
                    s[i][j] = fmaf(a[i].x, bb[j].x, s[i][j]);
                    s[i][j] = fmaf(a[i].y, bb[j].y, s[i][j]);
                    s[i][j] = fmaf(a[i].z, bb[j].z, s[i][j]);
                    s[i][j] = fmaf(a[i].w, bb[j].w, s[i][j]);
                }
        }

        // Online softmax: stats shared across the 16 tx lanes of each row.
        float mnew[4], corr[4];
#pragma unroll
        for (int i = 0; i < 4; i++) {
#pragma unroll
            for (int j = 0; j < 4; j++) s[i][j] *= SCALE;
            float mt = fmaxf(fmaxf(s[i][0], s[i][1]), fmaxf(s[i][2], s[i][3]));
#pragma unroll
            for (int off = 8; off > 0; off >>= 1)
                mt = fmaxf(mt, __shfl_xor_sync(0xffffffffu, mt, off));
            mnew[i] = fmaxf(m[i], mt);
            corr[i] = __expf(m[i] - mnew[i]);
            m[i] = mnew[i];
        }
#pragma unroll
        for (int i = 0; i < 4; i++) {
            float rs = 0.f;
#pragma unroll
            for (int j = 0; j < 4; j++) {
                float p = __expf(s[i][j] - mnew[i]);
                s[i][j] = p;
                rs += p;
            }
#pragma unroll
            for (int off = 8; off > 0; off >>= 1)
                rs += __shfl_xor_sync(0xffffffffu, rs, off);
            l[i] = l[i] * corr[i] + rs;
#pragma unroll
            for (int jj = 0; jj < 5; jj++) o[i][jj] *= corr[i];
        }

        // Write P transposed: Ps[kv][q]
#pragma unroll
        for (int j = 0; j < 4; j++)
#pragma unroll
            for (int i = 0; i < 4; i++)
                Ps[(tx * 4 + j) * PS_STR + ty * 4 + i] = s[i][j];
        __syncthreads();

        // O += P V  (rows ty*4+i, cols tx*5+jj)
#pragma unroll 4
        for (int k = 0; k < BNK; k++) {
            float pv[4], vv[5];
#pragma unroll
            for (int i = 0; i < 4; i++) pv[i] = Ps[k * PS_STR + ty * 4 + i];
#pragma unroll
            for (int jj = 0; jj < 5; jj++) vv[jj] = Vs[k * VS_STR + tx * 5 + jj];
#pragma unroll
            for (int i = 0; i < 4; i++)
#pragma unroll
                for (int jj = 0; jj < 5; jj++)
                    o[i][jj] = fmaf(pv[i], vv[jj], o[i][jj]);
        }
    }

    // Epilogue: normalize and store to [B,S,H*DH]
    float* og = g_attn + (b * S_ + q0) * D_ + h * DH_;
#pragma unroll
    for (int i = 0; i < 4; i++) {
        float inv = 1.0f / l[i];
#pragma unroll
        for (int jj = 0; jj < 5; jj++)
            og[(ty * 4 + i) * D_ + tx * 5 + jj] = o[i][jj] * inv;
    }
}

// ---------------------------------------------------------------------------
extern "C" void kernel_launch(void* const* d_in, const int* in_sizes, int n_in,
                              void* d_out, int out_size)
{
    const float* x   = (const float*)d_in[0];
    const float* enc = (const float*)d_in[1];
    const float* Wq  = (const float*)d_in[2];
    const float* Wk  = (const float*)d_in[3];
    const float* Wv  = (const float*)d_in[4];
    const float* Wo  = (const float*)d_in[5];
    const float* bo  = (const float*)d_in[6];
    float* out = (float*)d_out;

    float *qp, *kp, *vp, *ap;
    cudaGetSymbolAddress((void**)&qp, g_q);
    cudaGetSymbolAddress((void**)&kp, g_k);
    cudaGetSymbolAddress((void**)&vp, g_v);
    cudaGetSymbolAddress((void**)&ap, g_attn);

    cudaFuncSetAttribute(flash_attn_kernel,
                         cudaFuncAttributeMaxDynamicSharedMemorySize,
                         ATTN_SMEM_BYTES);

    dim3 gemm_grid(D_ / 64, M_ / 128);   // (10, 32)
    sgemm128x64<<<gemm_grid, 256>>>(x,   Wq, nullptr, qp, D_, D_);
    sgemm128x64<<<gemm_grid, 256>>>(enc, Wk, nullptr, kp, D_, D_);
    sgemm128x64<<<gemm_grid, 256>>>(enc, Wv, nullptr, vp, D_, D_);

    dim3 attn_grid(S_ / BMQ, H_, B_);    // (32, 8, 2)
    flash_attn_kernel<<<attn_grid, 256, ATTN_SMEM_BYTES>>>();

    sgemm128x64<<<gemm_grid, 256>>>(ap, Wo, bo, out, D_, D_);
}